// round 1
// baseline (speedup 1.0000x reference)
#include <cuda_runtime.h>

#define N_NODES  100000
#define N_EDGES  1600000
#define N_GRAPHS 1000
#define D        64

// ---------------- device scratch (no allocations allowed) ----------------
__device__ int   g_deg[N_NODES];
__device__ float g_dinv[N_NODES];
__device__ float g_h[(size_t)N_NODES * D];    // GEMM output buffer
__device__ float g_agg[(size_t)N_NODES * D];  // aggregation buffer

// ---------------- degree / norm ----------------
__global__ void k_deg_init() {
    int i = blockIdx.x * blockDim.x + threadIdx.x;
    if (i < N_NODES) g_deg[i] = 1;  // self-loop
}

__global__ void k_deg_count(const int* __restrict__ ei) {
    int e = blockIdx.x * blockDim.x + threadIdx.x;
    if (e < N_EDGES) atomicAdd(&g_deg[ei[N_EDGES + e]], 1);  // dst row
}

__global__ void k_dinv() {
    int i = blockIdx.x * blockDim.x + threadIdx.x;
    if (i < N_NODES) g_dinv[i] = rsqrtf((float)g_deg[i]);
}

// ---------------- 64x64 GEMM: out[N,64] = act(in)[N,64] @ W[64,64] ----------------
template<bool RELU_IN>
__global__ __launch_bounds__(256) void k_gemm64(const float* __restrict__ in,
                                                const float* __restrict__ W,
                                                float* __restrict__ out) {
    __shared__ float Xs[64][65];   // padded against bank conflicts
    __shared__ float Ws[64 * 64];

    int tid = threadIdx.x;                 // 256 threads
    int rowBase = blockIdx.x * 64;

    // stage W (16KB) via float4
    const float4* W4 = (const float4*)W;
    float4* Ws4 = (float4*)Ws;
#pragma unroll
    for (int i = 0; i < 4; i++) Ws4[tid + i * 256] = W4[tid + i * 256];

    // stage X tile (64 rows x 64 cols), optional relu on read
#pragma unroll
    for (int i = 0; i < 4; i++) {
        int f4 = tid + i * 256;            // 0..1023
        int r  = f4 >> 4;
        int c4 = f4 & 15;
        int row = rowBase + r;
        float4 v = make_float4(0.f, 0.f, 0.f, 0.f);
        if (row < N_NODES) v = ((const float4*)in)[row * 16 + c4];
        if (RELU_IN) {
            v.x = fmaxf(v.x, 0.f); v.y = fmaxf(v.y, 0.f);
            v.z = fmaxf(v.z, 0.f); v.w = fmaxf(v.w, 0.f);
        }
        Xs[r][c4 * 4 + 0] = v.x; Xs[r][c4 * 4 + 1] = v.y;
        Xs[r][c4 * 4 + 2] = v.z; Xs[r][c4 * 4 + 3] = v.w;
    }
    __syncthreads();

    int r  = tid >> 2;          // 0..63 (row within tile)
    int c0 = (tid & 3) << 4;    // 0,16,32,48 (col group)
    float acc[16];
#pragma unroll
    for (int c = 0; c < 16; c++) acc[c] = 0.f;

#pragma unroll 8
    for (int k = 0; k < 64; k++) {
        float xv = Xs[r][k];
#pragma unroll
        for (int q = 0; q < 4; q++) {
            float4 w = *(const float4*)&Ws[k * 64 + c0 + q * 4];
            acc[q * 4 + 0] += xv * w.x;
            acc[q * 4 + 1] += xv * w.y;
            acc[q * 4 + 2] += xv * w.z;
            acc[q * 4 + 3] += xv * w.w;
        }
    }

    int row = rowBase + r;
    if (row < N_NODES) {
#pragma unroll
        for (int q = 0; q < 4; q++)
            ((float4*)out)[row * 16 + (c0 >> 2) + q] =
                make_float4(acc[q * 4 + 0], acc[q * 4 + 1], acc[q * 4 + 2], acc[q * 4 + 3]);
    }
}

// ---------------- agg init: self-loop contribution + bias ----------------
// agg[n,d] = h[n,d] * dinv[n]^2 + b[d]
__global__ void k_selfinit(const float* __restrict__ h, const float* __restrict__ b,
                           float* __restrict__ agg) {
    int i = blockIdx.x * blockDim.x + threadIdx.x;  // float4 index
    if (i < N_NODES * 16) {
        int n = i >> 4;
        int d4 = i & 15;
        float s = g_dinv[n];
        s = s * s;
        float4 hv = ((const float4*)h)[i];
        float4 bv = ((const float4*)b)[d4];
        ((float4*)agg)[i] = make_float4(hv.x * s + bv.x, hv.y * s + bv.y,
                                        hv.z * s + bv.z, hv.w * s + bv.w);
    }
}

// ---------------- edge scatter-add: agg[dst] += h[src] * norm ----------------
// 16 lanes per edge, one float4 each, vectorized L2 reduction (red.v4.f32).
__global__ __launch_bounds__(256) void k_edge_agg(const int* __restrict__ ei,
                                                  const float* __restrict__ h,
                                                  float* __restrict__ agg) {
    int t = blockIdx.x * blockDim.x + threadIdx.x;
    int e = t >> 4;
    int lane = t & 15;
    if (e >= N_EDGES) return;
    int src = ei[e];
    int dst = ei[N_EDGES + e];
    float norm = g_dinv[src] * g_dinv[dst];
    float4 v = ((const float4*)h)[src * 16 + lane];
    float* p = agg + (size_t)dst * 64 + lane * 4;
    asm volatile("red.global.add.v4.f32 [%0], {%1, %2, %3, %4};"
                 :: "l"(p), "f"(v.x * norm), "f"(v.y * norm),
                    "f"(v.z * norm), "f"(v.w * norm)
                 : "memory");
}

// ---------------- fused mean-pool (batch is sorted) + MLP head ----------------
__global__ __launch_bounds__(64) void k_pool_head(const float* __restrict__ agg,
                                                  const int* __restrict__ batch,
                                                  const float* __restrict__ lw1,
                                                  const float* __restrict__ lb1,
                                                  const float* __restrict__ lw2,
                                                  const float* __restrict__ lb2,
                                                  float* __restrict__ out) {
    int g = blockIdx.x;
    int tid = threadIdx.x;  // 64

    // binary-search graph boundaries in the sorted batch array
    int l = 0, r = N_NODES;
    while (l < r) { int m = (l + r) >> 1; if (batch[m] < g) l = m + 1; else r = m; }
    int lo = l;
    r = N_NODES;
    while (l < r) { int m = (l + r) >> 1; if (batch[m] < g + 1) l = m + 1; else r = m; }
    int hi = l;

    float acc = 0.f;
    for (int n = lo; n < hi; n++) acc += agg[(size_t)n * 64 + tid];
    int cnt = hi - lo;
    float pooled = acc / (float)(cnt > 0 ? cnt : 1);

    __shared__ float sp[64];
    __shared__ float sz[32];
    sp[tid] = pooled;
    __syncthreads();

    if (tid < 32) {
        float z = lb1[tid];
#pragma unroll 8
        for (int k = 0; k < 64; k++) z += sp[k] * lw1[k * 32 + tid];
        sz[tid] = fmaxf(z, 0.f);
    }
    __syncthreads();

    if (tid < 8) {
        float o = lb2[tid];
#pragma unroll
        for (int j = 0; j < 32; j++) o += sz[j] * lw2[j * 8 + tid];
        out[g * 8 + tid] = o;
    }
}

// ---------------- launch ----------------
extern "C" void kernel_launch(void* const* d_in, const int* in_sizes, int n_in,
                              void* d_out, int out_size) {
    const float* x   = (const float*)d_in[0];
    const int*   ei  = (const int*)d_in[1];
    const int*   bat = (const int*)d_in[2];
    const float* W1  = (const float*)d_in[3];
    const float* b1  = (const float*)d_in[4];
    const float* W2  = (const float*)d_in[5];
    const float* b2  = (const float*)d_in[6];
    const float* lw1 = (const float*)d_in[7];
    const float* lb1 = (const float*)d_in[8];
    const float* lw2 = (const float*)d_in[9];
    const float* lb2 = (const float*)d_in[10];
    float* out = (float*)d_out;

    float *h, *agg;
    cudaGetSymbolAddress((void**)&h,   g_h);
    cudaGetSymbolAddress((void**)&agg, g_agg);

    // degrees + symmetric norm
    k_deg_init<<<(N_NODES + 255) / 256, 256>>>();
    k_deg_count<<<(N_EDGES + 255) / 256, 256>>>(ei);
    k_dinv<<<(N_NODES + 255) / 256, 256>>>();

    const int gemm_blocks = (N_NODES + 63) / 64;
    const int self_blocks = (N_NODES * 16 + 255) / 256;
    const int edge_blocks = (N_EDGES * 16 + 255) / 256;

    // layer 1: h = x @ W1 ; agg = scatter(h*norm) + self + b1 ; relu fused into next GEMM read
    k_gemm64<false><<<gemm_blocks, 256>>>(x, W1, h);
    k_selfinit<<<self_blocks, 256>>>(h, b1, agg);
    k_edge_agg<<<edge_blocks, 256>>>(ei, h, agg);

    // layer 2: h2 = relu(agg) @ W2 ; agg = scatter(h2*norm) + self + b2
    k_gemm64<true><<<gemm_blocks, 256>>>(agg, W2, h);
    k_selfinit<<<self_blocks, 256>>>(h, b2, agg);
    k_edge_agg<<<edge_blocks, 256>>>(ei, h, agg);

    // pool per graph + MLP head
    k_pool_head<<<N_GRAPHS, 64>>>(agg, bat, lw1, lb1, lw2, lb2, out);
}

// round 2
// speedup vs baseline: 1.5979x; 1.5979x over previous
#include <cuda_runtime.h>

#define N_NODES  100000
#define N_EDGES  1600000
#define N_GRAPHS 1000
#define D        64

// ---------------- device scratch (no allocations allowed) ----------------
__device__ int   g_deg[N_NODES];
__device__ float g_dinv[N_NODES];
__device__ float g_hs[(size_t)N_NODES * D];   // h * dinv[row]  (pre-scaled messages)
__device__ float g_agg[(size_t)N_NODES * D];  // aggregation buffer

// ---------------- degree / norm ----------------
__global__ void k_deg_init() {
    int i = blockIdx.x * blockDim.x + threadIdx.x;
    if (i < N_NODES) g_deg[i] = 1;  // self-loop
}

__global__ void k_deg_count(const int* __restrict__ ei) {
    int e = blockIdx.x * blockDim.x + threadIdx.x;
    if (e < N_EDGES) atomicAdd(&g_deg[ei[N_EDGES + e]], 1);  // dst row
}

__global__ void k_dinv() {
    int i = blockIdx.x * blockDim.x + threadIdx.x;
    if (i < N_NODES) g_dinv[i] = rsqrtf((float)g_deg[i]);
}

// ---------------- fused GEMM + self-loop/bias epilogue ----------------
// out = act(in)[N,64] @ W[64,64]
// hs[row]  = out[row] * dinv[row]
// agg[row] = out[row] * dinv[row]^2 + b     (self-loop init; edges RED into it)
//
// 128 threads, 128 rows per block. Thread computes an 8x8 register tile.
// X staged k-major in smem (XOR-swizzled 8-row groups), W staged row-major.
template<bool RELU_IN>
__global__ __launch_bounds__(128) void k_gcn_gemm(const float* __restrict__ in,
                                                  const float* __restrict__ W,
                                                  const float* __restrict__ bias,
                                                  float* __restrict__ hs,
                                                  float* __restrict__ agg) {
    __shared__ float Xt[64][128];   // [k][swizzled row]   32KB
    __shared__ float Ws[64][64];    // [k][col]            16KB

    const int tid = threadIdx.x;        // 0..127
    const int rowBase = blockIdx.x * 128;

    // ---- stage W: 1024 float4, 8 per thread ----
    {
        const float4* W4 = (const float4*)W;
        float4* Ws4 = (float4*)Ws;
#pragma unroll
        for (int i = 0; i < 8; i++) Ws4[tid + i * 128] = W4[tid + i * 128];
    }

    // ---- stage X transposed: 2048 float4 loads, 16 per thread ----
#pragma unroll
    for (int i = 0; i < 16; i++) {
        int f4  = tid + i * 128;        // 0..2047
        int r   = f4 >> 4;              // 0..127 (row within tile)
        int c4  = f4 & 15;              // float4 column (k group)
        int row = rowBase + r;
        float4 v = make_float4(0.f, 0.f, 0.f, 0.f);
        if (row < N_NODES) v = ((const float4*)in)[(size_t)row * 16 + c4];
        if (RELU_IN) {
            v.x = fmaxf(v.x, 0.f); v.y = fmaxf(v.y, 0.f);
            v.z = fmaxf(v.z, 0.f); v.w = fmaxf(v.w, 0.f);
        }
        // swizzle 8-row groups by c4 to spread STS banks; reads undo it per k
        int rsw = (((r >> 3) ^ c4) << 3) | (r & 7);
        Xt[c4 * 4 + 0][rsw] = v.x;
        Xt[c4 * 4 + 1][rsw] = v.y;
        Xt[c4 * 4 + 2][rsw] = v.z;
        Xt[c4 * 4 + 3][rsw] = v.w;
    }
    __syncthreads();

    const int rg  = tid >> 3;           // 0..15 -> rows rg*8..rg*8+7
    const int cg8 = (tid & 7) * 8;      // cols cg8..cg8+7

    float acc[8][8];
#pragma unroll
    for (int i = 0; i < 8; i++)
#pragma unroll
        for (int j = 0; j < 8; j++) acc[i][j] = 0.f;

#pragma unroll 8
    for (int k = 0; k < 64; k++) {
        int rgx = ((rg ^ (k >> 2)) << 3);
        float4 xa = *(const float4*)&Xt[k][rgx];
        float4 xb = *(const float4*)&Xt[k][rgx + 4];
        float4 wa = *(const float4*)&Ws[k][cg8];
        float4 wb = *(const float4*)&Ws[k][cg8 + 4];
        float xv[8] = {xa.x, xa.y, xa.z, xa.w, xb.x, xb.y, xb.z, xb.w};
        float wv[8] = {wa.x, wa.y, wa.z, wa.w, wb.x, wb.y, wb.z, wb.w};
#pragma unroll
        for (int i = 0; i < 8; i++)
#pragma unroll
            for (int j = 0; j < 8; j++)
                acc[i][j] += xv[i] * wv[j];
    }

    // ---- epilogue: hs = out*dinv, agg = out*dinv^2 + b ----
    float4 b0 = ((const float4*)bias)[(cg8 >> 2) + 0];
    float4 b1 = ((const float4*)bias)[(cg8 >> 2) + 1];

#pragma unroll
    for (int i = 0; i < 8; i++) {
        int row = rowBase + rg * 8 + i;
        if (row >= N_NODES) break;
        float di = g_dinv[row];
        float4 h0 = make_float4(acc[i][0] * di, acc[i][1] * di,
                                acc[i][2] * di, acc[i][3] * di);
        float4 h1 = make_float4(acc[i][4] * di, acc[i][5] * di,
                                acc[i][6] * di, acc[i][7] * di);
        size_t o = (size_t)row * 16 + (cg8 >> 2);
        ((float4*)hs)[o + 0] = h0;
        ((float4*)hs)[o + 1] = h1;
        ((float4*)agg)[o + 0] = make_float4(h0.x * di + b0.x, h0.y * di + b0.y,
                                            h0.z * di + b0.z, h0.w * di + b0.w);
        ((float4*)agg)[o + 1] = make_float4(h1.x * di + b1.x, h1.y * di + b1.y,
                                            h1.z * di + b1.z, h1.w * di + b1.w);
    }
}

// ---------------- edge scatter-add: agg[dst] += hs[src] * dinv[dst] ----------------
// 16 lanes per edge, one float4 each, vectorized L2 reduction (red.v4.f32).
__global__ __launch_bounds__(256) void k_edge_agg(const int* __restrict__ ei,
                                                  const float* __restrict__ hs,
                                                  float* __restrict__ agg) {
    int t = blockIdx.x * blockDim.x + threadIdx.x;
    int e = t >> 4;
    int lane = t & 15;
    if (e >= N_EDGES) return;
    int src = ei[e];
    int dst = ei[N_EDGES + e];
    float norm = g_dinv[dst];
    float4 v = ((const float4*)hs)[(size_t)src * 16 + lane];
    float* p = agg + (size_t)dst * 64 + lane * 4;
    asm volatile("red.global.add.v4.f32 [%0], {%1, %2, %3, %4};"
                 :: "l"(p), "f"(v.x * norm), "f"(v.y * norm),
                    "f"(v.z * norm), "f"(v.w * norm)
                 : "memory");
}

// ---------------- fused mean-pool (batch is sorted) + MLP head ----------------
__global__ __launch_bounds__(64) void k_pool_head(const float* __restrict__ agg,
                                                  const int* __restrict__ batch,
                                                  const float* __restrict__ lw1,
                                                  const float* __restrict__ lb1,
                                                  const float* __restrict__ lw2,
                                                  const float* __restrict__ lb2,
                                                  float* __restrict__ out) {
    int g = blockIdx.x;
    int tid = threadIdx.x;  // 64

    // binary-search graph boundaries in the sorted batch array
    int l = 0, r = N_NODES;
    while (l < r) { int m = (l + r) >> 1; if (batch[m] < g) l = m + 1; else r = m; }
    int lo = l;
    r = N_NODES;
    while (l < r) { int m = (l + r) >> 1; if (batch[m] < g + 1) l = m + 1; else r = m; }
    int hi = l;

    float acc = 0.f;
    for (int n = lo; n < hi; n++) acc += agg[(size_t)n * 64 + tid];
    int cnt = hi - lo;
    float pooled = acc / (float)(cnt > 0 ? cnt : 1);

    __shared__ float sp[64];
    __shared__ float sz[32];
    sp[tid] = pooled;
    __syncthreads();

    if (tid < 32) {
        float z = lb1[tid];
#pragma unroll 8
        for (int k = 0; k < 64; k++) z += sp[k] * lw1[k * 32 + tid];
        sz[tid] = fmaxf(z, 0.f);
    }
    __syncthreads();

    if (tid < 8) {
        float o = lb2[tid];
#pragma unroll
        for (int j = 0; j < 32; j++) o += sz[j] * lw2[j * 8 + tid];
        out[g * 8 + tid] = o;
    }
}

// ---------------- launch ----------------
extern "C" void kernel_launch(void* const* d_in, const int* in_sizes, int n_in,
                              void* d_out, int out_size) {
    const float* x   = (const float*)d_in[0];
    const int*   ei  = (const int*)d_in[1];
    const int*   bat = (const int*)d_in[2];
    const float* W1  = (const float*)d_in[3];
    const float* b1  = (const float*)d_in[4];
    const float* W2  = (const float*)d_in[5];
    const float* b2  = (const float*)d_in[6];
    const float* lw1 = (const float*)d_in[7];
    const float* lb1 = (const float*)d_in[8];
    const float* lw2 = (const float*)d_in[9];
    const float* lb2 = (const float*)d_in[10];
    float* out = (float*)d_out;

    float *hs, *agg;
    cudaGetSymbolAddress((void**)&hs,  g_hs);
    cudaGetSymbolAddress((void**)&agg, g_agg);

    // degrees + symmetric norm
    k_deg_init<<<(N_NODES + 255) / 256, 256>>>();
    k_deg_count<<<(N_EDGES + 255) / 256, 256>>>(ei);
    k_dinv<<<(N_NODES + 255) / 256, 256>>>();

    const int gemm_blocks = (N_NODES + 127) / 128;
    const int edge_blocks = (N_EDGES * 16 + 255) / 256;

    // layer 1: hs/agg from x @ W1 ; scatter edges
    k_gcn_gemm<false><<<gemm_blocks, 128>>>(x, W1, b1, hs, agg);
    k_edge_agg<<<edge_blocks, 256>>>(ei, hs, agg);

    // layer 2: hs/agg from relu(agg) @ W2 (in-place on agg rows) ; scatter edges
    k_gcn_gemm<true><<<gemm_blocks, 128>>>(agg, W2, b2, hs, agg);
    k_edge_agg<<<edge_blocks, 256>>>(ei, hs, agg);

    // pool per graph + MLP head
    k_pool_head<<<N_GRAPHS, 64>>>(agg, bat, lw1, lb1, lw2, lb2, out);
}

// round 3
// speedup vs baseline: 2.2294x; 1.3952x over previous
#include <cuda_runtime.h>

#define N_NODES  100000
#define N_EDGES  1600000
#define N_GRAPHS 1000
#define D        64
#define NB_SCAN  ((N_NODES + 255) / 256)   // 391

// ---------------- device scratch (no allocations allowed) ----------------
__device__ int   g_deg[N_NODES];
__device__ int   g_off[N_NODES];           // CSR row offsets (exclusive scan of deg-1)
__device__ int   g_cursor[N_NODES];        // fill cursors
__device__ int   g_bsum[NB_SCAN];          // scan block sums
__device__ int   g_boff[NB_SCAN];          // scanned block offsets
__device__ int   g_csr[N_EDGES];           // src indices grouped by dst
__device__ float g_dinv[N_NODES];
__device__ float g_hs[(size_t)N_NODES * D];   // h * dinv[row]  (pre-scaled messages)
__device__ float g_agg[(size_t)N_NODES * D];  // aggregation buffer

// ---------------- degree / norm ----------------
__global__ void k_deg_init() {
    int i = blockIdx.x * blockDim.x + threadIdx.x;
    if (i < N_NODES) g_deg[i] = 1;  // self-loop
}

__global__ void k_deg_count(const int* __restrict__ ei) {
    int e = blockIdx.x * blockDim.x + threadIdx.x;
    if (e < N_EDGES) atomicAdd(&g_deg[ei[N_EDGES + e]], 1);  // dst row
}

__global__ void k_dinv() {
    int i = blockIdx.x * blockDim.x + threadIdx.x;
    if (i < N_NODES) {
        g_dinv[i] = rsqrtf((float)g_deg[i]);
        g_cursor[i] = 0;
    }
}

// ---------------- 3-pass exclusive scan of (deg-1) into g_off ----------------
__global__ __launch_bounds__(256) void k_scanA() {
    __shared__ int s[256];
    int tid = threadIdx.x;
    int i = blockIdx.x * 256 + tid;
    int v = (i < N_NODES) ? (g_deg[i] - 1) : 0;
    s[tid] = v;
    __syncthreads();
#pragma unroll
    for (int o = 1; o < 256; o <<= 1) {
        int t = (tid >= o) ? s[tid - o] : 0;
        __syncthreads();
        s[tid] += t;
        __syncthreads();
    }
    if (i < N_NODES) g_off[i] = s[tid] - v;          // exclusive
    if (tid == 255) g_bsum[blockIdx.x] = s[255];
}

__global__ __launch_bounds__(512) void k_scanB() {
    __shared__ int s[512];
    int tid = threadIdx.x;
    int v = (tid < NB_SCAN) ? g_bsum[tid] : 0;
    s[tid] = v;
    __syncthreads();
#pragma unroll
    for (int o = 1; o < 512; o <<= 1) {
        int t = (tid >= o) ? s[tid - o] : 0;
        __syncthreads();
        s[tid] += t;
        __syncthreads();
    }
    if (tid < NB_SCAN) g_boff[tid] = s[tid] - v;     // exclusive
}

__global__ __launch_bounds__(256) void k_scanC() {
    int i = blockIdx.x * 256 + threadIdx.x;
    if (i < N_NODES) g_off[i] += g_boff[i >> 8];
}

// ---------------- CSR fill: group src indices by dst ----------------
__global__ __launch_bounds__(256) void k_fill(const int* __restrict__ ei) {
    int e = blockIdx.x * blockDim.x + threadIdx.x;
    if (e < N_EDGES) {
        int src = ei[e];
        int dst = ei[N_EDGES + e];
        int pos = g_off[dst] + atomicAdd(&g_cursor[dst], 1);
        g_csr[pos] = src;
    }
}

// ---------------- fused GEMM + self-loop/bias epilogue ----------------
// out = act(in)[N,64] @ W[64,64]
// hs[row]  = out[row] * dinv[row]
// agg[row] = out[row] * dinv[row]^2 + b     (self-loop init; gather adds edges)
template<bool RELU_IN>
__global__ __launch_bounds__(128) void k_gcn_gemm(const float* __restrict__ in,
                                                  const float* __restrict__ W,
                                                  const float* __restrict__ bias,
                                                  float* __restrict__ hs,
                                                  float* __restrict__ agg) {
    __shared__ float Xt[64][128];   // [k][swizzled row]   32KB
    __shared__ float Ws[64][64];    // [k][col]            16KB

    const int tid = threadIdx.x;        // 0..127
    const int rowBase = blockIdx.x * 128;

    // ---- stage W: 1024 float4, 8 per thread ----
    {
        const float4* W4 = (const float4*)W;
        float4* Ws4 = (float4*)Ws;
#pragma unroll
        for (int i = 0; i < 8; i++) Ws4[tid + i * 128] = W4[tid + i * 128];
    }

    // ---- stage X transposed: 2048 float4 loads, 16 per thread ----
#pragma unroll
    for (int i = 0; i < 16; i++) {
        int f4  = tid + i * 128;        // 0..2047
        int r   = f4 >> 4;              // 0..127 (row within tile)
        int c4  = f4 & 15;              // float4 column (k group)
        int row = rowBase + r;
        float4 v = make_float4(0.f, 0.f, 0.f, 0.f);
        if (row < N_NODES) v = ((const float4*)in)[(size_t)row * 16 + c4];
        if (RELU_IN) {
            v.x = fmaxf(v.x, 0.f); v.y = fmaxf(v.y, 0.f);
            v.z = fmaxf(v.z, 0.f); v.w = fmaxf(v.w, 0.f);
        }
        int rsw = (((r >> 3) ^ c4) << 3) | (r & 7);
        Xt[c4 * 4 + 0][rsw] = v.x;
        Xt[c4 * 4 + 1][rsw] = v.y;
        Xt[c4 * 4 + 2][rsw] = v.z;
        Xt[c4 * 4 + 3][rsw] = v.w;
    }
    __syncthreads();

    const int rg  = tid >> 3;           // 0..15 -> rows rg*8..rg*8+7
    const int cg8 = (tid & 7) * 8;      // cols cg8..cg8+7

    float acc[8][8];
#pragma unroll
    for (int i = 0; i < 8; i++)
#pragma unroll
        for (int j = 0; j < 8; j++) acc[i][j] = 0.f;

#pragma unroll 8
    for (int k = 0; k < 64; k++) {
        int rgx = ((rg ^ (k >> 2)) << 3);
        float4 xa = *(const float4*)&Xt[k][rgx];
        float4 xb = *(const float4*)&Xt[k][rgx + 4];
        float4 wa = *(const float4*)&Ws[k][cg8];
        float4 wb = *(const float4*)&Ws[k][cg8 + 4];
        float xv[8] = {xa.x, xa.y, xa.z, xa.w, xb.x, xb.y, xb.z, xb.w};
        float wv[8] = {wa.x, wa.y, wa.z, wa.w, wb.x, wb.y, wb.z, wb.w};
#pragma unroll
        for (int i = 0; i < 8; i++)
#pragma unroll
            for (int j = 0; j < 8; j++)
                acc[i][j] += xv[i] * wv[j];
    }

    // ---- epilogue: hs = out*dinv, agg = out*dinv^2 + b ----
    float4 b0 = ((const float4*)bias)[(cg8 >> 2) + 0];
    float4 b1 = ((const float4*)bias)[(cg8 >> 2) + 1];

#pragma unroll
    for (int i = 0; i < 8; i++) {
        int row = rowBase + rg * 8 + i;
        if (row >= N_NODES) break;
        float di = g_dinv[row];
        float4 h0 = make_float4(acc[i][0] * di, acc[i][1] * di,
                                acc[i][2] * di, acc[i][3] * di);
        float4 h1 = make_float4(acc[i][4] * di, acc[i][5] * di,
                                acc[i][6] * di, acc[i][7] * di);
        size_t o = (size_t)row * 16 + (cg8 >> 2);
        ((float4*)hs)[o + 0] = h0;
        ((float4*)hs)[o + 1] = h1;
        ((float4*)agg)[o + 0] = make_float4(h0.x * di + b0.x, h0.y * di + b0.y,
                                            h0.z * di + b0.z, h0.w * di + b0.w);
        ((float4*)agg)[o + 1] = make_float4(h1.x * di + b1.x, h1.y * di + b1.y,
                                            h1.z * di + b1.z, h1.w * di + b1.w);
    }
}

// ---------------- CSR gather: agg[n] += dinv[n] * sum_{src in csr[n]} hs[src] ----------------
// 16 lanes per node, one float4 each; 2 independent accumulator chains for ILP.
__global__ __launch_bounds__(256) void k_gather(const float* __restrict__ hs,
                                                float* __restrict__ agg) {
    int t = blockIdx.x * blockDim.x + threadIdx.x;
    int node = t >> 4;
    int lane = t & 15;
    if (node >= N_NODES) return;

    int start = g_off[node];
    int cnt   = g_deg[node] - 1;

    float4 a0 = make_float4(0.f, 0.f, 0.f, 0.f);
    float4 a1 = make_float4(0.f, 0.f, 0.f, 0.f);

    int i = 0;
    for (; i + 2 <= cnt; i += 2) {
        int s0 = g_csr[start + i];
        int s1 = g_csr[start + i + 1];
        float4 v0 = ((const float4*)hs)[(size_t)s0 * 16 + lane];
        float4 v1 = ((const float4*)hs)[(size_t)s1 * 16 + lane];
        a0.x += v0.x; a0.y += v0.y; a0.z += v0.z; a0.w += v0.w;
        a1.x += v1.x; a1.y += v1.y; a1.z += v1.z; a1.w += v1.w;
    }
    if (i < cnt) {
        int s0 = g_csr[start + i];
        float4 v0 = ((const float4*)hs)[(size_t)s0 * 16 + lane];
        a0.x += v0.x; a0.y += v0.y; a0.z += v0.z; a0.w += v0.w;
    }

    float dv = g_dinv[node];
    size_t o = (size_t)node * 16 + lane;
    float4 cur = ((float4*)agg)[o];
    cur.x += dv * (a0.x + a1.x);
    cur.y += dv * (a0.y + a1.y);
    cur.z += dv * (a0.z + a1.z);
    cur.w += dv * (a0.w + a1.w);
    ((float4*)agg)[o] = cur;
}

// ---------------- fused mean-pool (batch is sorted) + MLP head ----------------
__global__ __launch_bounds__(64) void k_pool_head(const float* __restrict__ agg,
                                                  const int* __restrict__ batch,
                                                  const float* __restrict__ lw1,
                                                  const float* __restrict__ lb1,
                                                  const float* __restrict__ lw2,
                                                  const float* __restrict__ lb2,
                                                  float* __restrict__ out) {
    int g = blockIdx.x;
    int tid = threadIdx.x;  // 64

    int l = 0, r = N_NODES;
    while (l < r) { int m = (l + r) >> 1; if (batch[m] < g) l = m + 1; else r = m; }
    int lo = l;
    r = N_NODES;
    while (l < r) { int m = (l + r) >> 1; if (batch[m] < g + 1) l = m + 1; else r = m; }
    int hi = l;

    float acc = 0.f;
    for (int n = lo; n < hi; n++) acc += agg[(size_t)n * 64 + tid];
    int cnt = hi - lo;
    float pooled = acc / (float)(cnt > 0 ? cnt : 1);

    __shared__ float sp[64];
    __shared__ float sz[32];
    sp[tid] = pooled;
    __syncthreads();

    if (tid < 32) {
        float z = lb1[tid];
#pragma unroll 8
        for (int k = 0; k < 64; k++) z += sp[k] * lw1[k * 32 + tid];
        sz[tid] = fmaxf(z, 0.f);
    }
    __syncthreads();

    if (tid < 8) {
        float o = lb2[tid];
#pragma unroll
        for (int j = 0; j < 32; j++) o += sz[j] * lw2[j * 8 + tid];
        out[g * 8 + tid] = o;
    }
}

// ---------------- launch ----------------
extern "C" void kernel_launch(void* const* d_in, const int* in_sizes, int n_in,
                              void* d_out, int out_size) {
    const float* x   = (const float*)d_in[0];
    const int*   ei  = (const int*)d_in[1];
    const int*   bat = (const int*)d_in[2];
    const float* W1  = (const float*)d_in[3];
    const float* b1  = (const float*)d_in[4];
    const float* W2  = (const float*)d_in[5];
    const float* b2  = (const float*)d_in[6];
    const float* lw1 = (const float*)d_in[7];
    const float* lb1 = (const float*)d_in[8];
    const float* lw2 = (const float*)d_in[9];
    const float* lb2 = (const float*)d_in[10];
    float* out = (float*)d_out;

    float *hs, *agg;
    cudaGetSymbolAddress((void**)&hs,  g_hs);
    cudaGetSymbolAddress((void**)&agg, g_agg);

    const int nblk = (N_NODES + 255) / 256;
    const int eblk = (N_EDGES + 255) / 256;

    // degrees + symmetric norm + CSR build
    k_deg_init<<<nblk, 256>>>();
    k_deg_count<<<eblk, 256>>>(ei);
    k_dinv<<<nblk, 256>>>();
    k_scanA<<<NB_SCAN, 256>>>();
    k_scanB<<<1, 512>>>();
    k_scanC<<<nblk, 256>>>();
    k_fill<<<eblk, 256>>>(ei);

    const int gemm_blocks = (N_NODES + 127) / 128;
    const int gath_blocks = (N_NODES * 16 + 255) / 256;

    // layer 1
    k_gcn_gemm<false><<<gemm_blocks, 128>>>(x, W1, b1, hs, agg);
    k_gather<<<gath_blocks, 256>>>(hs, agg);

    // layer 2 (in-place read of agg rows)
    k_gcn_gemm<true><<<gemm_blocks, 128>>>(agg, W2, b2, hs, agg);
    k_gather<<<gath_blocks, 256>>>(hs, agg);

    // pool per graph + MLP head
    k_pool_head<<<N_GRAPHS, 64>>>(agg, bat, lw1, lb1, lw2, lb2, out);
}